// round 16
// baseline (speedup 1.0000x reference)
#include <cuda_runtime.h>
#include <cuda_fp16.h>
#include <cstdint>

#define NN 40000        // nodes
#define NE 640000       // edges
#define D 128
#define D2 256
#define LTOK 10
#define NLAYERS 5
#define GG 512          // graphs
#define BN_EPS 1e-5f
#define LOSCALE 2048.0f
#define INV_LOSCALE (1.0f / 2048.0f)
#define MBLK 313        // ceil(NN/128)
#define GEMM_SMEM 74240  // gemm1: 3 stages x 24KB + pad
#define GEMM2_SMEM 61952 // gemm2: 3 stages x 20KB + 256B bn partials

// ---------------- scratch (static device globals; no allocation) ----------------
__device__ float g_h[NN * D];
__device__ float g_z2[NN * D];
__device__ float g_sumL[NLAYERS * D], g_sumsqL[NLAYERS * D];
__device__ float g_gsum[GG * D];
__device__ float g_gcnt[GG];
// CSR (by dst)
__device__ int g_deg[NN];
__device__ int g_off[NN + 1];
__device__ int g_cursor[NN];
__device__ int g_csr[NE];            // src*16 + edge_type
// fragment-order fp16 hi/lo activations (u32 = f16x2)
__device__ uint32_t g_za_h[MBLK * 4 * 2048], g_za_l[MBLK * 4 * 2048];  // z  (KD=128)
__device__ uint32_t g_mf_h[MBLK * 8 * 2048], g_mf_l[MBLK * 8 * 2048];  // mid(KD=256)
// fragment-packed fp16 hi/lo weights (W2 packed at 32-col granularity)
__device__ uint32_t g_w1h[NLAYERS * D * D2 / 2], g_w1l[NLAYERS * D * D2 / 2];
__device__ uint32_t g_w2h[NLAYERS * D2 * D / 2], g_w2l[NLAYERS * D2 * D / 2];

// ---------------- helpers ----------------
#define MMA_F16(ACC, A0, A1, A2, A3, B0, B1)                                   \
    asm volatile(                                                              \
        "mma.sync.aligned.m16n8k16.row.col.f32.f16.f16.f32 "                   \
        "{%0,%1,%2,%3}, {%4,%5,%6,%7}, {%8,%9}, {%0,%1,%2,%3};"                \
        : "+f"(ACC[0]), "+f"(ACC[1]), "+f"(ACC[2]), "+f"(ACC[3])               \
        : "r"(A0), "r"(A1), "r"(A2), "r"(A3), "r"(B0), "r"(B1))

#define MMA_F16ACC(AC2, A0, A1, A2, A3, B0, B1)                                \
    asm volatile(                                                              \
        "mma.sync.aligned.m16n8k16.row.col.f16.f16.f16.f16 "                   \
        "{%0,%1}, {%2,%3,%4,%5}, {%6,%7}, {%0,%1};"                            \
        : "+r"(AC2[0]), "+r"(AC2[1])                                           \
        : "r"(A0), "r"(A1), "r"(A2), "r"(A3), "r"(B0), "r"(B1))

__device__ __forceinline__ uint32_t pack_h2(__half a, __half b) {
    __half2 h = __halves2half2(a, b);
    return *(uint32_t*)&h;
}
__device__ __forceinline__ void split_pair(float v0, float v1,
                                           uint32_t& hi, uint32_t& lo) {
    __half h0 = __float2half_rn(v0), h1 = __float2half_rn(v1);
    hi = pack_h2(h0, h1);
    lo = pack_h2(__float2half_rn((v0 - __half2float(h0)) * LOSCALE),
                 __float2half_rn((v1 - __half2float(h1)) * LOSCALE));
}
__device__ __forceinline__ uint32_t smem_u32(const void* p) {
    uint32_t a;
    asm("{ .reg .u64 t; cvta.to.shared.u64 t, %1; cvt.u32.u64 %0, t; }" : "=r"(a) : "l"(p));
    return a;
}
__device__ __forceinline__ void cp16(uint32_t dst, const void* src) {
    asm volatile("cp.async.cg.shared.global [%0], [%1], 16;" :: "r"(dst), "l"(src));
}
#define CP_COMMIT() asm volatile("cp.async.commit_group;" ::: "memory")

// ---------------- zero (must precede prolog's hist atomics) ----------------
__global__ void zero_pool_kernel() {
    int i = blockIdx.x * blockDim.x + threadIdx.x;
    if (i < GG * D) g_gsum[i] = 0.f;
    if (i < GG) g_gcnt[i] = 0.f;
    if (i < NN) g_deg[i] = 0;
    if (i < NLAYERS * D) { g_sumL[i] = 0.f; g_sumsqL[i] = 0.f; }
}

// ---------------- wsplit element ----------------
__device__ __forceinline__ void wsplit_elem(int idx, const float* __restrict__ W1,
                                            const float* __restrict__ W2) {
    const int T1 = NLAYERS * D * D2;
    if (idx < T1) {            // W1: [l][k:128][n:256], packed at 64-col granularity
        int l = idx / (D * D2), r = idx % (D * D2);
        int k = r / D2, n = r % D2;
        float v = W1[idx];
        __half hi = __float2half_rn(v);
        __half lo = __float2half_rn((v - __half2float(hi)) * LOSCALE);
        int nb = n >> 6, kc = k >> 5, k5 = k & 31;
        int kk = k5 >> 4, k16 = k5 & 15;
        int reg = (k16 >> 3) & 1, tig = (k16 & 7) >> 1, pos = k16 & 1;
        int lane = (n & 7) * 4 + tig, nj8 = (n >> 3) & 7;
        long du = (long)l * (D * D2 / 2) +
                  ((((nb * (D / 32) + kc) * 2 + kk) * 8 + nj8) * 32 + lane) * 2 + reg;
        ((__half*)g_w1h)[du * 2 + pos] = hi;
        ((__half*)g_w1l)[du * 2 + pos] = lo;
    } else if (idx < 2 * T1) { // W2: [l][k:256][n:128], packed at 32-col granularity
        int j = idx - T1;
        int l = j / (D2 * D), r = j % (D2 * D);
        int k = r / D, n = r % D;
        float v = W2[j];
        __half hi = __float2half_rn(v);
        __half lo = __float2half_rn((v - __half2float(hi)) * LOSCALE);
        int nb = n >> 5, kc = k >> 5, k5 = k & 31;
        int kk = k5 >> 4, k16 = k5 & 15;
        int reg = (k16 >> 3) & 1, tig = (k16 & 7) >> 1, pos = k16 & 1;
        int lane = (n & 7) * 4 + tig, nj8 = (n >> 3) & 3;
        long du = (long)l * (D2 * D / 2) +
                  ((((nb * (D2 / 32) + kc) * 2 + kk) * 4 + nj8) * 32 + lane) * 2 + reg;
        ((__half*)g_w2h)[du * 2 + pos] = hi;
        ((__half*)g_w2l)[du * 2 + pos] = lo;
    }
}

// ---------------- mega prolog: WordBag + graph-count + hist + wsplit ----------------
__global__ void prolog_kernel(const int* __restrict__ x_tokens,
                              const int* __restrict__ ins_len,
                              const float* __restrict__ wemb,
                              const int* __restrict__ batch_ids,
                              const int* __restrict__ edge_index,
                              const float* __restrict__ W1,
                              const float* __restrict__ W2) {
    int n = blockIdx.x;
    int d = threadIdx.x;
    __shared__ int toks[LTOK];
    __shared__ int len_s;
    if (d < LTOK) toks[d] = x_tokens[n * LTOK + d];
    if (d == 0) {
        len_s = ins_len[n];
        atomicAdd(&g_gcnt[batch_ids[n]], 1.0f);
    }
    if (d < 16) atomicAdd(&g_deg[edge_index[NE + n * 16 + d]], 1);
    if (d >= 16 && d < 48) {
        int idx = n * 32 + (d - 16);
        if (idx < 2 * NLAYERS * D * D2) wsplit_elem(idx, W1, W2);
    }
    __syncthreads();
    int len = len_s;
    float acc = 0.f;
    for (int l = 0; l < len; l++)
        acc += wemb[(long)toks[l] * D + d];
    g_h[n * D + d] = acc / (float)len;
}

// ---------------- CSR scan + fill ----------------
__global__ void scan_kernel() {
    __shared__ int ssum[1024];
    int tid = threadIdx.x;
    int s = 0;
#pragma unroll 4
    for (int i = 0; i < 40; i++) {
        int idx = tid * 40 + i;
        if (idx < NN) s += g_deg[idx];
    }
    ssum[tid] = s;
    __syncthreads();
    for (int off = 1; off < 1024; off <<= 1) {
        int v = (tid >= off) ? ssum[tid - off] : 0;
        __syncthreads();
        ssum[tid] += v;
        __syncthreads();
    }
    int run = (tid > 0) ? ssum[tid - 1] : 0;
    for (int i = 0; i < 40; i++) {
        int idx = tid * 40 + i;
        if (idx < NN) {
            g_off[idx] = run;
            g_cursor[idx] = run;
            run += g_deg[idx];
        }
    }
    if (tid == 1023) g_off[NN] = NE;
}
__global__ void fill_kernel(const int* __restrict__ edge_index,
                            const int* __restrict__ edge_attr) {
    int e = blockIdx.x * blockDim.x + threadIdx.x;
    if (e >= NE) return;
    int dst = edge_index[NE + e];
    int pos = atomicAdd(&g_cursor[dst], 1);
    g_csr[pos] = edge_index[e] * 16 + edge_attr[e];
}

// ---------------- aggregation (+ in-block BN finalize of previous layer) ----------------
template<int FUSED>
__global__ void aggregate_kernel(const float* __restrict__ eemb,
                                 const float* __restrict__ src,
                                 const float* __restrict__ sumS,
                                 const float* __restrict__ sumQ,
                                 const float* __restrict__ gamma,
                                 const float* __restrict__ beta) {
    __shared__ __align__(16) float ssc[D], ssh[D];
    int tid = threadIdx.x;
    if (FUSED) {
        if (tid < D) {
            float mu = sumS[tid] * (1.0f / NN);
            float var = sumQ[tid] * (1.0f / NN) - mu * mu;
            float rs = rsqrtf(var + BN_EPS);
            float sc = gamma[tid] * rs;
            ssc[tid] = sc;
            ssh[tid] = beta[tid] - mu * sc;
        }
        __syncthreads();
    }
    int warp = (blockIdx.x * blockDim.x + tid) >> 5;
    int lane = tid & 31;
    if (warp >= NN) return;
    int n = warp;
    float4 sc4, sh4;
    if (FUSED) {
        sc4 = *(const float4*)(ssc + lane * 4);
        sh4 = *(const float4*)(ssh + lane * 4);
    }
    float4 acc = *(const float4*)(src + (long)n * D + lane * 4);
    if (FUSED) {
        acc.x = fmaxf(fmaf(sc4.x, acc.x, sh4.x), 0.f);
        acc.y = fmaxf(fmaf(sc4.y, acc.y, sh4.y), 0.f);
        acc.z = fmaxf(fmaf(sc4.z, acc.z, sh4.z), 0.f);
        acc.w = fmaxf(fmaf(sc4.w, acc.w, sh4.w), 0.f);
    }
    int s = g_off[n], e = g_off[n + 1];
    int i = s;
    int nb4 = (e - s) >> 2;
    for (int b = 0; b < nb4; b++, i += 4) {
        int p0 = g_csr[i], p1 = g_csr[i + 1], p2 = g_csr[i + 2], p3 = g_csr[i + 3];
        float4 h0 = *(const float4*)(src + (long)(p0 >> 4) * D + lane * 4);
        float4 h1 = *(const float4*)(src + (long)(p1 >> 4) * D + lane * 4);
        float4 h2 = *(const float4*)(src + (long)(p2 >> 4) * D + lane * 4);
        float4 h3 = *(const float4*)(src + (long)(p3 >> 4) * D + lane * 4);
        float4 e0 = __ldg((const float4*)(eemb + (p0 & 15) * D + lane * 4));
        float4 e1 = __ldg((const float4*)(eemb + (p1 & 15) * D + lane * 4));
        float4 e2 = __ldg((const float4*)(eemb + (p2 & 15) * D + lane * 4));
        float4 e3 = __ldg((const float4*)(eemb + (p3 & 15) * D + lane * 4));
        if (FUSED) {
            h0.x = fmaxf(fmaf(sc4.x, h0.x, sh4.x), 0.f); h0.y = fmaxf(fmaf(sc4.y, h0.y, sh4.y), 0.f);
            h0.z = fmaxf(fmaf(sc4.z, h0.z, sh4.z), 0.f); h0.w = fmaxf(fmaf(sc4.w, h0.w, sh4.w), 0.f);
            h1.x = fmaxf(fmaf(sc4.x, h1.x, sh4.x), 0.f); h1.y = fmaxf(fmaf(sc4.y, h1.y, sh4.y), 0.f);
            h1.z = fmaxf(fmaf(sc4.z, h1.z, sh4.z), 0.f); h1.w = fmaxf(fmaf(sc4.w, h1.w, sh4.w), 0.f);
            h2.x = fmaxf(fmaf(sc4.x, h2.x, sh4.x), 0.f); h2.y = fmaxf(fmaf(sc4.y, h2.y, sh4.y), 0.f);
            h2.z = fmaxf(fmaf(sc4.z, h2.z, sh4.z), 0.f); h2.w = fmaxf(fmaf(sc4.w, h2.w, sh4.w), 0.f);
            h3.x = fmaxf(fmaf(sc4.x, h3.x, sh4.x), 0.f); h3.y = fmaxf(fmaf(sc4.y, h3.y, sh4.y), 0.f);
            h3.z = fmaxf(fmaf(sc4.z, h3.z, sh4.z), 0.f); h3.w = fmaxf(fmaf(sc4.w, h3.w, sh4.w), 0.f);
        }
        acc.x += (h0.x + e0.x) + (h1.x + e1.x) + (h2.x + e2.x) + (h3.x + e3.x);
        acc.y += (h0.y + e0.y) + (h1.y + e1.y) + (h2.y + e2.y) + (h3.y + e3.y);
        acc.z += (h0.z + e0.z) + (h1.z + e1.z) + (h2.z + e2.z) + (h3.z + e3.z);
        acc.w += (h0.w + e0.w) + (h1.w + e1.w) + (h2.w + e2.w) + (h3.w + e3.w);
    }
    for (; i < e; i++) {
        int p = g_csr[i];
        float4 hv = *(const float4*)(src + (long)(p >> 4) * D + lane * 4);
        if (FUSED) {
            hv.x = fmaxf(fmaf(sc4.x, hv.x, sh4.x), 0.f);
            hv.y = fmaxf(fmaf(sc4.y, hv.y, sh4.y), 0.f);
            hv.z = fmaxf(fmaf(sc4.z, hv.z, sh4.z), 0.f);
            hv.w = fmaxf(fmaf(sc4.w, hv.w, sh4.w), 0.f);
        }
        float4 ev = __ldg((const float4*)(eemb + (p & 15) * D + lane * 4));
        acc.x += hv.x + ev.x; acc.y += hv.y + ev.y;
        acc.z += hv.z + ev.z; acc.w += hv.w + ev.w;
    }
    int mb = n >> 7, r = n & 127;
    int t = r >> 4, gidw = r & 7, rh = (r >> 3) & 1;
#pragma unroll
    for (int p = 0; p < 2; p++) {
        int j = 2 * lane + p;
        int kc = j >> 4, kk = (j >> 3) & 1, tig = j & 3;
        int reg = rh + 2 * ((j >> 2) & 1);
        long idx = ((long)(mb * 4 + kc)) * 2048 +
                   ((kk * 8 + t) * 32 + gidw * 4 + tig) * 4 + reg;
        uint32_t hi, lo;
        split_pair(p ? acc.z : acc.x, p ? acc.w : acc.y, hi, lo);
        g_za_h[idx] = hi;
        g_za_l[idx] = lo;
    }
}

// ---------------- GEMM1: fp16-split, 3-stage cp.async, frag-out (mid) ----------------
__global__ void __launch_bounds__(256, 2)
gemm1_kernel(const uint32_t* __restrict__ Ah, const uint32_t* __restrict__ Al,
             const uint32_t* __restrict__ Bhi, const uint32_t* __restrict__ Blo,
             const float* __restrict__ bias,
             uint32_t* __restrict__ Fh, uint32_t* __restrict__ Fl) {
    constexpr int KC = D / 32;   // 4
    extern __shared__ uint32_t dsm[];
    uint32_t sbase = smem_u32(dsm);
    int tid = threadIdx.x, lane = tid & 31, warp = tid >> 5;
    int wm = warp >> 1, wn = warp & 1;
    int bx = blockIdx.x, nb = blockIdx.y;
    int m0 = bx * 128, n0 = nb * 64;

    float acc[2][4][4];
    uint32_t acx[2][4][2];
#pragma unroll
    for (int i = 0; i < 2; i++)
#pragma unroll
        for (int j = 0; j < 4; j++) {
#pragma unroll
            for (int q = 0; q < 4; q++) acc[i][j][q] = 0.f;
            acx[i][j][0] = 0u; acx[i][j][1] = 0u;
        }

    auto prefetch = [&](int kc, int st) {
        uint32_t sb = sbase + st * 24576;
        const uint4* ah = (const uint4*)(Ah + ((long)(bx * KC + kc)) * 2048);
        const uint4* al = (const uint4*)(Al + ((long)(bx * KC + kc)) * 2048);
        cp16(sb + tid * 16, ah + tid);
        cp16(sb + (tid + 256) * 16, ah + tid + 256);
        cp16(sb + 8192 + tid * 16, al + tid);
        cp16(sb + 8192 + (tid + 256) * 16, al + tid + 256);
        const uint4* bh = (const uint4*)(Bhi + ((long)(nb * KC + kc)) * 1024);
        const uint4* bl = (const uint4*)(Blo + ((long)(nb * KC + kc)) * 1024);
        cp16(sb + 16384 + tid * 16, bh + tid);
        cp16(sb + 20480 + tid * 16, bl + tid);
        CP_COMMIT();
    };

    prefetch(0, 0);
    prefetch(1, 1);
    for (int kc = 0; kc < KC; kc++) {
        int st = kc % 3;
        if (kc + 1 < KC)
            asm volatile("cp.async.wait_group 1;" ::: "memory");
        else
            asm volatile("cp.async.wait_group 0;" ::: "memory");
        __syncthreads();
        if (kc + 2 < KC) prefetch(kc + 2, (kc + 2) % 3);
        uint32_t* As = dsm + st * 6144;
        uint32_t* Bs = dsm + st * 6144 + 4096;
#pragma unroll
        for (int kk = 0; kk < 2; kk++) {
            uint32_t aH[2][4], aL[2][4];
#pragma unroll
            for (int mi = 0; mi < 2; mi++) {
                int tt = wm * 2 + mi;
                const uint4 h = *(const uint4*)&As[((kk * 8 + tt) * 32 + lane) * 4];
                const uint4 l = *(const uint4*)&As[2048 + ((kk * 8 + tt) * 32 + lane) * 4];
                aH[mi][0] = h.x; aH[mi][1] = h.y; aH[mi][2] = h.z; aH[mi][3] = h.w;
                aL[mi][0] = l.x; aL[mi][1] = l.y; aL[mi][2] = l.z; aL[mi][3] = l.w;
            }
            uint32_t bH[4][2], bL[4][2];
#pragma unroll
            for (int nj = 0; nj < 4; nj++) {
                int nj8 = wn * 4 + nj;
                const uint2 h = *(const uint2*)&Bs[((kk * 8 + nj8) * 32 + lane) * 2];
                const uint2 l = *(const uint2*)&Bs[1024 + ((kk * 8 + nj8) * 32 + lane) * 2];
                bH[nj][0] = h.x; bH[nj][1] = h.y;
                bL[nj][0] = l.x; bL[nj][1] = l.y;
            }
#pragma unroll
            for (int mi = 0; mi < 2; mi++)
#pragma unroll
                for (int nj = 0; nj < 4; nj++)
                    MMA_F16(acc[mi][nj], aH[mi][0], aH[mi][1], aH[mi][2], aH[mi][3],
                            bH[nj][0], bH[nj][1]);
#pragma unroll
            for (int mi = 0; mi < 2; mi++)
#pragma unroll
                for (int nj = 0; nj < 4; nj++)
                    MMA_F16ACC(acx[mi][nj], aH[mi][0], aH[mi][1], aH[mi][2], aH[mi][3],
                               bL[nj][0], bL[nj][1]);
#pragma unroll
            for (int mi = 0; mi < 2; mi++)
#pragma unroll
                for (int nj = 0; nj < 4; nj++)
                    MMA_F16ACC(acx[mi][nj], aL[mi][0], aL[mi][1], aL[mi][2], aL[mi][3],
                               bH[nj][0], bH[nj][1]);
        }
    }
    __syncthreads();

    int gid = lane >> 2, tig = lane & 3;
#pragma unroll
    for (int mi = 0; mi < 2; mi++) {
        int r0 = m0 + wm * 32 + mi * 16 + gid;
#pragma unroll
        for (int nj = 0; nj < 4; nj++) {
            int col = n0 + wn * 32 + nj * 8 + 2 * tig;
            float bi0 = bias[col], bi1 = bias[col + 1];
            __half2 x01 = *(__half2*)&acx[mi][nj][0];
            __half2 x23 = *(__half2*)&acx[mi][nj][1];
            float v0 = fmaxf(acc[mi][nj][0] + __half2float(__low2half(x01))  * INV_LOSCALE + bi0, 0.f);
            float v1 = fmaxf(acc[mi][nj][1] + __half2float(__high2half(x01)) * INV_LOSCALE + bi1, 0.f);
            float v2 = fmaxf(acc[mi][nj][2] + __half2float(__low2half(x23))  * INV_LOSCALE + bi0, 0.f);
            float v3 = fmaxf(acc[mi][nj][3] + __half2float(__high2half(x23)) * INV_LOSCALE + bi1, 0.f);
            int r = r0 & 127;
            int t = r >> 4, gidw = r & 7, rh = (r >> 3) & 1;
            int j = col >> 1;
            int kk2 = (j >> 3) & 1, tig2 = j & 3;
            int regb = 2 * ((j >> 2) & 1);
            int base = wn * 2048 + ((kk2 * 8 + t) * 32 + gidw * 4 + tig2) * 4;
            uint32_t hi, lo;
            split_pair(v0, v1, hi, lo);
            dsm[base + rh + regb] = hi;
            dsm[4096 + base + rh + regb] = lo;
            split_pair(v2, v3, hi, lo);
            dsm[base + (rh ^ 1) + regb] = hi;
            dsm[4096 + base + (rh ^ 1) + regb] = lo;
        }
    }
    __syncthreads();
    long gb = ((long)(bx * 8 + nb * 2)) * 2048;
    uint4* dh = (uint4*)(Fh + gb);
    uint4* dl = (uint4*)(Fl + gb);
    const uint4* sh_ = (const uint4*)dsm;
    const uint4* sl_ = (const uint4*)(dsm + 4096);
#pragma unroll
    for (int i = 0; i < 4; i++) {
        dh[tid + i * 256] = sh_[tid + i * 256];
        dl[tid + i * 256] = sl_[tid + i * 256];
    }
}

// ---------------- GEMM2: BN=32 tiles (grid 313x4), fp32 C + fused BN stats ----------------
// stage (20KB = 5120 u32): A hi [0,2048), A lo [2048,4096), B hi [4096,4608), B lo [4608,5120)
__global__ void __launch_bounds__(256, 2)
gemm2_kernel(const uint32_t* __restrict__ Ah, const uint32_t* __restrict__ Al,
             const uint32_t* __restrict__ Bhi, const uint32_t* __restrict__ Blo,
             const float* __restrict__ bias, float* __restrict__ C,
             float* __restrict__ sumS, float* __restrict__ sumQ) {
    constexpr int KC = D2 / 32;   // 8
    extern __shared__ uint32_t dsm[];
    float* bnS = (float*)(dsm + 15360);
    float* bnQ = bnS + 32;
    uint32_t sbase = smem_u32(dsm);
    int tid = threadIdx.x, lane = tid & 31, warp = tid >> 5;   // warp = t (row group)
    int bx = blockIdx.x, nb = blockIdx.y;
    int m0 = bx * 128, n0 = nb * 32;

    if (tid < 32) { bnS[tid] = 0.f; bnQ[tid] = 0.f; }

    float acc[4][4];
    uint32_t acx[4][2];
#pragma unroll
    for (int j = 0; j < 4; j++) {
#pragma unroll
        for (int q = 0; q < 4; q++) acc[j][q] = 0.f;
        acx[j][0] = 0u; acx[j][1] = 0u;
    }

    auto prefetch = [&](int kc, int st) {
        uint32_t sb = sbase + st * 20480;
        const uint4* ah = (const uint4*)(Ah + ((long)(bx * KC + kc)) * 2048);
        const uint4* al = (const uint4*)(Al + ((long)(bx * KC + kc)) * 2048);
        cp16(sb + tid * 16, ah + tid);
        cp16(sb + (tid + 256) * 16, ah + tid + 256);
        cp16(sb + 8192 + tid * 16, al + tid);
        cp16(sb + 8192 + (tid + 256) * 16, al + tid + 256);
        if (tid < 128) {
            const uint4* bh = (const uint4*)(Bhi + ((long)(nb * KC + kc)) * 512);
            const uint4* bl = (const uint4*)(Blo + ((long)(nb * KC + kc)) * 512);
            cp16(sb + 16384 + tid * 16, bh + tid);
            cp16(sb + 18432 + tid * 16, bl + tid);
        }
        CP_COMMIT();
    };

    prefetch(0, 0);
    prefetch(1, 1);
    for (int kc = 0; kc < KC; kc++) {
        int st = kc % 3;
        if (kc + 1 < KC)
            asm volatile("cp.async.wait_group 1;" ::: "memory");
        else
            asm volatile("cp.async.wait_group 0;" ::: "memory");
        __syncthreads();
        if (kc + 2 < KC) prefetch(kc + 2, (kc + 2) % 3);
        uint32_t* As = dsm + st * 5120;
        uint32_t* Bs = dsm + st * 5120 + 4096;
#pragma unroll
        for (int kk = 0; kk < 2; kk++) {
            uint32_t aH[4], aL[4];
            {
                const uint4 h = *(const uint4*)&As[((kk * 8 + warp) * 32 + lane) * 4];
                const uint4 l = *(const uint4*)&As[2048 + ((kk * 8 + warp) * 32 + lane) * 4];
                aH[0] = h.x; aH[1] = h.y; aH[2] = h.z; aH[3] = h.w;
                aL[0] = l.x; aL[1] = l.y; aL[2] = l.z; aL[3] = l.w;
            }
            uint32_t bH[4][2], bL[4][2];
#pragma unroll
            for (int nj = 0; nj < 4; nj++) {
                const uint2 h = *(const uint2*)&Bs[((kk * 4 + nj) * 32 + lane) * 2];
                const uint2 l = *(const uint2*)&Bs[512 + ((kk * 4 + nj) * 32 + lane) * 2];
                bH[nj][0] = h.x; bH[nj][1] = h.y;
                bL[nj][0] = l.x; bL[nj][1] = l.y;
            }
#pragma unroll
            for (int nj = 0; nj < 4; nj++)
                MMA_F16(acc[nj], aH[0], aH[1], aH[2], aH[3], bH[nj][0], bH[nj][1]);
#pragma unroll
            for (int nj = 0; nj < 4; nj++)
                MMA_F16ACC(acx[nj], aH[0], aH[1], aH[2], aH[3], bL[nj][0], bL[nj][1]);
#pragma unroll
            for (int nj = 0; nj < 4; nj++)
                MMA_F16ACC(acx[nj], aL[0], aL[1], aL[2], aL[3], bH[nj][0], bH[nj][1]);
        }
    }
    __syncthreads();

    int gid = lane >> 2, tig = lane & 3;
    int r0 = m0 + warp * 16 + gid;
    bool valid = (r0 < NN);    // 16-row groups all-in/out (NN % 16 == 0)
    float sA[4][2], qA[4][2];
#pragma unroll
    for (int nj = 0; nj < 4; nj++) {
        sA[nj][0] = sA[nj][1] = 0.f;
        qA[nj][0] = qA[nj][1] = 0.f;
    }
#pragma unroll
    for (int nj = 0; nj < 4; nj++) {
        int col = n0 + nj * 8 + 2 * tig;
        float bi0 = bias[col], bi1 = bias[col + 1];
        __half2 x01 = *(__half2*)&acx[nj][0];
        __half2 x23 = *(__half2*)&acx[nj][1];
        float v0 = acc[nj][0] + __half2float(__low2half(x01))  * INV_LOSCALE + bi0;
        float v1 = acc[nj][1] + __half2float(__high2half(x01)) * INV_LOSCALE + bi1;
        float v2 = acc[nj][2] + __half2float(__low2half(x23))  * INV_LOSCALE + bi0;
        float v3 = acc[nj][3] + __half2float(__high2half(x23)) * INV_LOSCALE + bi1;
        if (valid) {
            *(float2*)(C + (long)r0 * D + col)       = make_float2(v0, v1);
            *(float2*)(C + (long)(r0 + 8) * D + col) = make_float2(v2, v3);
            sA[nj][0] += v0 + v2; qA[nj][0] += v0 * v0 + v2 * v2;
            sA[nj][1] += v1 + v3; qA[nj][1] += v1 * v1 + v3 * v3;
        }
    }
#pragma unroll
    for (int nj = 0; nj < 4; nj++) {
#pragma unroll
        for (int m = 4; m < 32; m <<= 1) {
            sA[nj][0] += __shfl_xor_sync(0xFFFFFFFF, sA[nj][0], m);
            sA[nj][1] += __shfl_xor_sync(0xFFFFFFFF, sA[nj][1], m);
            qA[nj][0] += __shfl_xor_sync(0xFFFFFFFF, qA[nj][0], m);
            qA[nj][1] += __shfl_xor_sync(0xFFFFFFFF, qA[nj][1], m);
        }
        if (lane < 4) {
            int c = nj * 8 + 2 * lane;
            atomicAdd(&bnS[c],     sA[nj][0]);
            atomicAdd(&bnS[c + 1], sA[nj][1]);
            atomicAdd(&bnQ[c],     qA[nj][0]);
            atomicAdd(&bnQ[c + 1], qA[nj][1]);
        }
    }
    __syncthreads();
    if (tid < 32) {
        atomicAdd(&sumS[n0 + tid], bnS[tid]);
        atomicAdd(&sumQ[n0 + tid], bnQ[tid]);
    }
}

// ---------------- last-layer BN apply: node_rep + pool RED ----------------
__global__ void bn_apply_last_kernel(const float* __restrict__ gamma,
                                     const float* __restrict__ beta,
                                     const int* __restrict__ batch_ids,
                                     const float* __restrict__ sumS,
                                     const float* __restrict__ sumQ,
                                     float* __restrict__ out_node) {
    __shared__ __align__(16) float ssc[D], ssh[D];
    int tid = threadIdx.x;
    if (tid < D) {
        float mu = sumS[tid] * (1.0f / NN);
        float var = sumQ[tid] * (1.0f / NN) - mu * mu;
        float rs = rsqrtf(var + BN_EPS);
        float sc = gamma[tid] * rs;
        ssc[tid] = sc;
        ssh[tid] = beta[tid] - mu * sc;
    }
    __syncthreads();
    int idx = blockIdx.x * blockDim.x + tid;
    if (idx >= NN * 32) return;
    int row = idx >> 5;
    int d0  = (idx & 31) * 4;
    float4 x = *(const float4*)(g_z2 + (long)row * D + d0);
    float4 sc = *(const float4*)(ssc + d0);
    float4 sh = *(const float4*)(ssh + d0);
    float4 o;
    o.x = fmaf(sc.x, x.x, sh.x);
    o.y = fmaf(sc.y, x.y, sh.y);
    o.z = fmaf(sc.z, x.z, sh.z);
    o.w = fmaf(sc.w, x.w, sh.w);
    *(float4*)(out_node + (long)row * D + d0) = o;
    int b = batch_ids[row];
    float* gp = g_gsum + (long)b * D + d0;
    asm volatile("red.global.add.v4.f32 [%0], {%1,%2,%3,%4};"
                 :: "l"(gp), "f"(o.x), "f"(o.y), "f"(o.z), "f"(o.w) : "memory");
}
__global__ void pool_finalize_kernel(float* __restrict__ out) {
    int i = blockIdx.x * blockDim.x + threadIdx.x;
    if (i >= GG * D) return;
    int g = i >> 7;
    out[i] = g_gsum[i] / fmaxf(g_gcnt[g], 1.0f);
}

// ---------------- launch ----------------
extern "C" void kernel_launch(void* const* d_in, const int* in_sizes, int n_in,
                              void* d_out, int out_size) {
    const int* x_tokens   = (const int*)d_in[0];
    const int* ins_len    = (const int*)d_in[1];
    const int* edge_index = (const int*)d_in[2];
    const int* edge_attr  = (const int*)d_in[3];
    const int* batch_ids  = (const int*)d_in[4];
    const float* wemb  = (const float*)d_in[5];
    const float* eemb  = (const float*)d_in[6];
    const float* W1    = (const float*)d_in[7];
    const float* b1    = (const float*)d_in[8];
    const float* W2    = (const float*)d_in[9];
    const float* b2    = (const float*)d_in[10];
    const float* gamma = (const float*)d_in[11];
    const float* beta  = (const float*)d_in[12];
    float* out = (float*)d_out;
    float* out_graph = out;                 // [GG, D]
    float* out_node  = out + GG * D;        // [NN, D]

    float *ph, *pz2, *psum, *psumsq;
    uint32_t *pzah, *pzal, *pmfh, *pmfl, *pw1h, *pw1l, *pw2h, *pw2l;
    cudaGetSymbolAddress((void**)&ph,     g_h);
    cudaGetSymbolAddress((void**)&pz2,    g_z2);
    cudaGetSymbolAddress((void**)&psum,   g_sumL);
    cudaGetSymbolAddress((void**)&psumsq, g_sumsqL);
    cudaGetSymbolAddress((void**)&pzah, g_za_h);
    cudaGetSymbolAddress((void**)&pzal, g_za_l);
    cudaGetSymbolAddress((void**)&pmfh, g_mf_h);
    cudaGetSymbolAddress((void**)&pmfl, g_mf_l);
    cudaGetSymbolAddress((void**)&pw1h, g_w1h);
    cudaGetSymbolAddress((void**)&pw1l, g_w1l);
    cudaGetSymbolAddress((void**)&pw2h, g_w2h);
    cudaGetSymbolAddress((void**)&pw2l, g_w2l);

    cudaFuncSetAttribute(gemm1_kernel,
                         cudaFuncAttributeMaxDynamicSharedMemorySize, GEMM_SMEM);
    cudaFuncSetAttribute(gemm2_kernel,
                         cudaFuncAttributeMaxDynamicSharedMemorySize, GEMM2_SMEM);

    zero_pool_kernel<<<(GG * D + 255) / 256, 256>>>();
    prolog_kernel<<<NN, 128>>>(x_tokens, ins_len, wemb, batch_ids,
                               edge_index, W1, W2);
    scan_kernel<<<1, 1024>>>();
    fill_kernel<<<(NE + 255) / 256, 256>>>(edge_index, edge_attr);

    for (int l = 0; l < NLAYERS; l++) {
        if (l == 0)
            aggregate_kernel<0><<<NN / 8, 256>>>(eemb, ph, nullptr, nullptr,
                                                 nullptr, nullptr);
        else
            aggregate_kernel<1><<<NN / 8, 256>>>(eemb, pz2,
                                                 psum + (long)(l - 1) * D,
                                                 psumsq + (long)(l - 1) * D,
                                                 gamma + (long)(l - 1) * D,
                                                 beta + (long)(l - 1) * D);
        gemm1_kernel<<<dim3(MBLK, 4), 256, GEMM_SMEM>>>(
            pzah, pzal, pw1h + (long)l * D * D2 / 2, pw1l + (long)l * D * D2 / 2,
            b1 + (long)l * D2, pmfh, pmfl);
        gemm2_kernel<<<dim3(MBLK, 4), 256, GEMM2_SMEM>>>(
            pmfh, pmfl, pw2h + (long)l * D2 * D / 2, pw2l + (long)l * D2 * D / 2,
            b2 + (long)l * D, pz2, psum + (long)l * D, psumsq + (long)l * D);
    }
    bn_apply_last_kernel<<<(NN * 32 + 255) / 256, 256>>>(
        gamma + (long)(NLAYERS - 1) * D, beta + (long)(NLAYERS - 1) * D,
        batch_ids, psum + (long)(NLAYERS - 1) * D, psumsq + (long)(NLAYERS - 1) * D,
        out_node);

    pool_finalize_kernel<<<(GG * D + 255) / 256, 256>>>(out_graph);
}

// round 17
// speedup vs baseline: 1.0689x; 1.0689x over previous
#include <cuda_runtime.h>
#include <cuda_fp16.h>
#include <cstdint>

#define NN 40000        // nodes
#define NE 640000       // edges
#define D 128
#define D2 256
#define LTOK 10
#define NLAYERS 5
#define GG 512          // graphs
#define BN_EPS 1e-5f
#define LOSCALE 2048.0f
#define INV_LOSCALE (1.0f / 2048.0f)
#define MBLK 313        // ceil(NN/128)
#define GEMM_SMEM 74240 // 3 stages x 24KB + 512B bn partials

// ---------------- scratch (static device globals; no allocation) ----------------
__device__ float g_h[NN * D];
__device__ float g_z2[NN * D];
__device__ float g_sumL[NLAYERS * D], g_sumsqL[NLAYERS * D];
__device__ float g_gsum[GG * D];
__device__ float g_gcnt[GG];
// CSR (by dst)
__device__ int g_deg[NN];
__device__ int g_off[NN + 1];
__device__ int g_cursor[NN];
__device__ int g_csr[NE];            // src*16 + edge_type
// fragment-order fp16 hi/lo activations (u32 = f16x2)
__device__ uint32_t g_za_h[MBLK * 4 * 2048], g_za_l[MBLK * 4 * 2048];  // z  (KD=128)
__device__ uint32_t g_mf_h[MBLK * 8 * 2048], g_mf_l[MBLK * 8 * 2048];  // mid(KD=256)
// fragment-packed fp16 hi/lo weights (both at 64-col granularity)
__device__ uint32_t g_w1h[NLAYERS * D * D2 / 2], g_w1l[NLAYERS * D * D2 / 2];
__device__ uint32_t g_w2h[NLAYERS * D2 * D / 2], g_w2l[NLAYERS * D2 * D / 2];

// ---------------- helpers ----------------
#define MMA_F16(ACC, A0, A1, A2, A3, B0, B1)                                   \
    asm volatile(                                                              \
        "mma.sync.aligned.m16n8k16.row.col.f32.f16.f16.f32 "                   \
        "{%0,%1,%2,%3}, {%4,%5,%6,%7}, {%8,%9}, {%0,%1,%2,%3};"                \
        : "+f"(ACC[0]), "+f"(ACC[1]), "+f"(ACC[2]), "+f"(ACC[3])               \
        : "r"(A0), "r"(A1), "r"(A2), "r"(A3), "r"(B0), "r"(B1))

#define MMA_F16ACC(AC2, A0, A1, A2, A3, B0, B1)                                \
    asm volatile(                                                              \
        "mma.sync.aligned.m16n8k16.row.col.f16.f16.f16.f16 "                   \
        "{%0,%1}, {%2,%3,%4,%5}, {%6,%7}, {%0,%1};"                            \
        : "+r"(AC2[0]), "+r"(AC2[1])                                           \
        : "r"(A0), "r"(A1), "r"(A2), "r"(A3), "r"(B0), "r"(B1))

__device__ __forceinline__ uint32_t pack_h2(__half a, __half b) {
    __half2 h = __halves2half2(a, b);
    return *(uint32_t*)&h;
}
__device__ __forceinline__ void split_pair(float v0, float v1,
                                           uint32_t& hi, uint32_t& lo) {
    __half h0 = __float2half_rn(v0), h1 = __float2half_rn(v1);
    hi = pack_h2(h0, h1);
    lo = pack_h2(__float2half_rn((v0 - __half2float(h0)) * LOSCALE),
                 __float2half_rn((v1 - __half2float(h1)) * LOSCALE));
}
__device__ __forceinline__ uint32_t smem_u32(const void* p) {
    uint32_t a;
    asm("{ .reg .u64 t; cvta.to.shared.u64 t, %1; cvt.u32.u64 %0, t; }" : "=r"(a) : "l"(p));
    return a;
}
__device__ __forceinline__ void cp16(uint32_t dst, const void* src) {
    asm volatile("cp.async.cg.shared.global [%0], [%1], 16;" :: "r"(dst), "l"(src));
}
#define CP_COMMIT() asm volatile("cp.async.commit_group;" ::: "memory")

// ---------------- zero (must precede prolog's hist atomics) ----------------
__global__ void zero_pool_kernel() {
    int i = blockIdx.x * blockDim.x + threadIdx.x;
    if (i < GG * D) g_gsum[i] = 0.f;
    if (i < GG) g_gcnt[i] = 0.f;
    if (i < NN) g_deg[i] = 0;
    if (i < NLAYERS * D) { g_sumL[i] = 0.f; g_sumsqL[i] = 0.f; }
}

// ---------------- wsplit element ----------------
__device__ __forceinline__ void wsplit_elem(int idx, const float* __restrict__ W1,
                                            const float* __restrict__ W2) {
    const int T1 = NLAYERS * D * D2;
    if (idx < T1) {            // W1: [l][k:128][n:256]
        int l = idx / (D * D2), r = idx % (D * D2);
        int k = r / D2, n = r % D2;
        float v = W1[idx];
        __half hi = __float2half_rn(v);
        __half lo = __float2half_rn((v - __half2float(hi)) * LOSCALE);
        int nb = n >> 6, kc = k >> 5, k5 = k & 31;
        int kk = k5 >> 4, k16 = k5 & 15;
        int reg = (k16 >> 3) & 1, tig = (k16 & 7) >> 1, pos = k16 & 1;
        int lane = (n & 7) * 4 + tig, nj8 = (n >> 3) & 7;
        long du = (long)l * (D * D2 / 2) +
                  ((((nb * (D / 32) + kc) * 2 + kk) * 8 + nj8) * 32 + lane) * 2 + reg;
        ((__half*)g_w1h)[du * 2 + pos] = hi;
        ((__half*)g_w1l)[du * 2 + pos] = lo;
    } else if (idx < 2 * T1) { // W2: [l][k:256][n:128]
        int j = idx - T1;
        int l = j / (D2 * D), r = j % (D2 * D);
        int k = r / D, n = r % D;
        float v = W2[j];
        __half hi = __float2half_rn(v);
        __half lo = __float2half_rn((v - __half2float(hi)) * LOSCALE);
        int nb = n >> 6, kc = k >> 5, k5 = k & 31;
        int kk = k5 >> 4, k16 = k5 & 15;
        int reg = (k16 >> 3) & 1, tig = (k16 & 7) >> 1, pos = k16 & 1;
        int lane = (n & 7) * 4 + tig, nj8 = (n >> 3) & 7;
        long du = (long)l * (D2 * D / 2) +
                  ((((nb * (D2 / 32) + kc) * 2 + kk) * 8 + nj8) * 32 + lane) * 2 + reg;
        ((__half*)g_w2h)[du * 2 + pos] = hi;
        ((__half*)g_w2l)[du * 2 + pos] = lo;
    }
}

// ---------------- mega prolog: WordBag + graph-count + hist + wsplit ----------------
__global__ void prolog_kernel(const int* __restrict__ x_tokens,
                              const int* __restrict__ ins_len,
                              const float* __restrict__ wemb,
                              const int* __restrict__ batch_ids,
                              const int* __restrict__ edge_index,
                              const float* __restrict__ W1,
                              const float* __restrict__ W2) {
    int n = blockIdx.x;
    int d = threadIdx.x;
    __shared__ int toks[LTOK];
    __shared__ int len_s;
    if (d < LTOK) toks[d] = x_tokens[n * LTOK + d];
    if (d == 0) {
        len_s = ins_len[n];
        atomicAdd(&g_gcnt[batch_ids[n]], 1.0f);
    }
    if (d < 16) atomicAdd(&g_deg[edge_index[NE + n * 16 + d]], 1);
    if (d >= 16 && d < 48) {
        int idx = n * 32 + (d - 16);
        if (idx < 2 * NLAYERS * D * D2) wsplit_elem(idx, W1, W2);
    }
    __syncthreads();
    int len = len_s;
    float acc = 0.f;
    for (int l = 0; l < len; l++)
        acc += wemb[(long)toks[l] * D + d];
    g_h[n * D + d] = acc / (float)len;
}

// ---------------- CSR scan + fill ----------------
__global__ void scan_kernel() {
    __shared__ int ssum[1024];
    int tid = threadIdx.x;
    int s = 0;
#pragma unroll 4
    for (int i = 0; i < 40; i++) {
        int idx = tid * 40 + i;
        if (idx < NN) s += g_deg[idx];
    }
    ssum[tid] = s;
    __syncthreads();
    for (int off = 1; off < 1024; off <<= 1) {
        int v = (tid >= off) ? ssum[tid - off] : 0;
        __syncthreads();
        ssum[tid] += v;
        __syncthreads();
    }
    int run = (tid > 0) ? ssum[tid - 1] : 0;
    for (int i = 0; i < 40; i++) {
        int idx = tid * 40 + i;
        if (idx < NN) {
            g_off[idx] = run;
            g_cursor[idx] = run;
            run += g_deg[idx];
        }
    }
    if (tid == 1023) g_off[NN] = NE;
}
__global__ void fill_kernel(const int* __restrict__ edge_index,
                            const int* __restrict__ edge_attr) {
    int e = (blockIdx.x * blockDim.x + threadIdx.x) * 2;
    if (e >= NE) return;
    int d0 = edge_index[NE + e], d1 = edge_index[NE + e + 1];
    int s0 = edge_index[e],      s1 = edge_index[e + 1];
    int a0 = edge_attr[e],       a1 = edge_attr[e + 1];
    int p0 = atomicAdd(&g_cursor[d0], 1);
    int p1 = atomicAdd(&g_cursor[d1], 1);
    g_csr[p0] = s0 * 16 + a0;
    g_csr[p1] = s1 * 16 + a1;
}

// ---------------- aggregation (+ in-block BN finalize of previous layer) ----------------
template<int FUSED>
__global__ void aggregate_kernel(const float* __restrict__ eemb,
                                 const float* __restrict__ src,
                                 const float* __restrict__ sumS,
                                 const float* __restrict__ sumQ,
                                 const float* __restrict__ gamma,
                                 const float* __restrict__ beta) {
    __shared__ __align__(16) float ssc[D], ssh[D];
    int tid = threadIdx.x;
    if (FUSED) {
        if (tid < D) {
            float mu = sumS[tid] * (1.0f / NN);
            float var = sumQ[tid] * (1.0f / NN) - mu * mu;
            float rs = rsqrtf(var + BN_EPS);
            float sc = gamma[tid] * rs;
            ssc[tid] = sc;
            ssh[tid] = beta[tid] - mu * sc;
        }
        __syncthreads();
    }
    int warp = (blockIdx.x * blockDim.x + tid) >> 5;
    int lane = tid & 31;
    if (warp >= NN) return;
    int n = warp;
    float4 sc4, sh4;
    if (FUSED) {
        sc4 = *(const float4*)(ssc + lane * 4);
        sh4 = *(const float4*)(ssh + lane * 4);
    }
    float4 acc = *(const float4*)(src + (long)n * D + lane * 4);
    if (FUSED) {
        acc.x = fmaxf(fmaf(sc4.x, acc.x, sh4.x), 0.f);
        acc.y = fmaxf(fmaf(sc4.y, acc.y, sh4.y), 0.f);
        acc.z = fmaxf(fmaf(sc4.z, acc.z, sh4.z), 0.f);
        acc.w = fmaxf(fmaf(sc4.w, acc.w, sh4.w), 0.f);
    }
    int s = g_off[n], e = g_off[n + 1];
    int i = s;
    int nb4 = (e - s) >> 2;
    for (int b = 0; b < nb4; b++, i += 4) {
        int p0 = g_csr[i], p1 = g_csr[i + 1], p2 = g_csr[i + 2], p3 = g_csr[i + 3];
        float4 h0 = *(const float4*)(src + (long)(p0 >> 4) * D + lane * 4);
        float4 h1 = *(const float4*)(src + (long)(p1 >> 4) * D + lane * 4);
        float4 h2 = *(const float4*)(src + (long)(p2 >> 4) * D + lane * 4);
        float4 h3 = *(const float4*)(src + (long)(p3 >> 4) * D + lane * 4);
        float4 e0 = __ldg((const float4*)(eemb + (p0 & 15) * D + lane * 4));
        float4 e1 = __ldg((const float4*)(eemb + (p1 & 15) * D + lane * 4));
        float4 e2 = __ldg((const float4*)(eemb + (p2 & 15) * D + lane * 4));
        float4 e3 = __ldg((const float4*)(eemb + (p3 & 15) * D + lane * 4));
        if (FUSED) {
            h0.x = fmaxf(fmaf(sc4.x, h0.x, sh4.x), 0.f); h0.y = fmaxf(fmaf(sc4.y, h0.y, sh4.y), 0.f);
            h0.z = fmaxf(fmaf(sc4.z, h0.z, sh4.z), 0.f); h0.w = fmaxf(fmaf(sc4.w, h0.w, sh4.w), 0.f);
            h1.x = fmaxf(fmaf(sc4.x, h1.x, sh4.x), 0.f); h1.y = fmaxf(fmaf(sc4.y, h1.y, sh4.y), 0.f);
            h1.z = fmaxf(fmaf(sc4.z, h1.z, sh4.z), 0.f); h1.w = fmaxf(fmaf(sc4.w, h1.w, sh4.w), 0.f);
            h2.x = fmaxf(fmaf(sc4.x, h2.x, sh4.x), 0.f); h2.y = fmaxf(fmaf(sc4.y, h2.y, sh4.y), 0.f);
            h2.z = fmaxf(fmaf(sc4.z, h2.z, sh4.z), 0.f); h2.w = fmaxf(fmaf(sc4.w, h2.w, sh4.w), 0.f);
            h3.x = fmaxf(fmaf(sc4.x, h3.x, sh4.x), 0.f); h3.y = fmaxf(fmaf(sc4.y, h3.y, sh4.y), 0.f);
            h3.z = fmaxf(fmaf(sc4.z, h3.z, sh4.z), 0.f); h3.w = fmaxf(fmaf(sc4.w, h3.w, sh4.w), 0.f);
        }
        acc.x += (h0.x + e0.x) + (h1.x + e1.x) + (h2.x + e2.x) + (h3.x + e3.x);
        acc.y += (h0.y + e0.y) + (h1.y + e1.y) + (h2.y + e2.y) + (h3.y + e3.y);
        acc.z += (h0.z + e0.z) + (h1.z + e1.z) + (h2.z + e2.z) + (h3.z + e3.z);
        acc.w += (h0.w + e0.w) + (h1.w + e1.w) + (h2.w + e2.w) + (h3.w + e3.w);
    }
    for (; i < e; i++) {
        int p = g_csr[i];
        float4 hv = *(const float4*)(src + (long)(p >> 4) * D + lane * 4);
        if (FUSED) {
            hv.x = fmaxf(fmaf(sc4.x, hv.x, sh4.x), 0.f);
            hv.y = fmaxf(fmaf(sc4.y, hv.y, sh4.y), 0.f);
            hv.z = fmaxf(fmaf(sc4.z, hv.z, sh4.z), 0.f);
            hv.w = fmaxf(fmaf(sc4.w, hv.w, sh4.w), 0.f);
        }
        float4 ev = __ldg((const float4*)(eemb + (p & 15) * D + lane * 4));
        acc.x += hv.x + ev.x; acc.y += hv.y + ev.y;
        acc.z += hv.z + ev.z; acc.w += hv.w + ev.w;
    }
    int mb = n >> 7, r = n & 127;
    int t = r >> 4, gidw = r & 7, rh = (r >> 3) & 1;
#pragma unroll
    for (int p = 0; p < 2; p++) {
        int j = 2 * lane + p;
        int kc = j >> 4, kk = (j >> 3) & 1, tig = j & 3;
        int reg = rh + 2 * ((j >> 2) & 1);
        long idx = ((long)(mb * 4 + kc)) * 2048 +
                   ((kk * 8 + t) * 32 + gidw * 4 + tig) * 4 + reg;
        uint32_t hi, lo;
        split_pair(p ? acc.z : acc.x, p ? acc.w : acc.y, hi, lo);
        g_za_h[idx] = hi;
        g_za_l[idx] = lo;
    }
}

// ---------------- fp16-split GEMM, 3-stage cp.async pipeline (R15 proven) ----------------
template<int NT, int KD, int OUT>
__global__ void __launch_bounds__(256, 2)
gemm_f16_kernel(const uint32_t* __restrict__ Ah, const uint32_t* __restrict__ Al,
                const uint32_t* __restrict__ Bhi, const uint32_t* __restrict__ Blo,
                const float* __restrict__ bias, float* __restrict__ C,
                uint32_t* __restrict__ Fh, uint32_t* __restrict__ Fl,
                float* __restrict__ sumS, float* __restrict__ sumQ) {
    constexpr int KC = KD / 32;
    extern __shared__ uint32_t dsm[];
    float* bnS = (float*)(dsm + 18432);
    float* bnQ = bnS + 64;
    uint32_t sbase = smem_u32(dsm);
    int tid = threadIdx.x, lane = tid & 31, warp = tid >> 5;
    int wm = warp >> 1, wn = warp & 1;
    int bx = blockIdx.x, nb = blockIdx.y;
    int m0 = bx * 128, n0 = nb * 64;

    if (OUT == 0 && tid < 64) { bnS[tid] = 0.f; bnQ[tid] = 0.f; }

    float acc[2][4][4];
    uint32_t acx[2][4][2];
#pragma unroll
    for (int i = 0; i < 2; i++)
#pragma unroll
        for (int j = 0; j < 4; j++) {
#pragma unroll
            for (int q = 0; q < 4; q++) acc[i][j][q] = 0.f;
            acx[i][j][0] = 0u; acx[i][j][1] = 0u;
        }

    auto prefetch = [&](int kc, int st) {
        uint32_t sb = sbase + st * 24576;
        const uint4* ah = (const uint4*)(Ah + ((long)(bx * KC + kc)) * 2048);
        const uint4* al = (const uint4*)(Al + ((long)(bx * KC + kc)) * 2048);
        cp16(sb + tid * 16, ah + tid);
        cp16(sb + (tid + 256) * 16, ah + tid + 256);
        cp16(sb + 8192 + tid * 16, al + tid);
        cp16(sb + 8192 + (tid + 256) * 16, al + tid + 256);
        const uint4* bh = (const uint4*)(Bhi + ((long)(nb * KC + kc)) * 1024);
        const uint4* bl = (const uint4*)(Blo + ((long)(nb * KC + kc)) * 1024);
        cp16(sb + 16384 + tid * 16, bh + tid);
        cp16(sb + 20480 + tid * 16, bl + tid);
        CP_COMMIT();
    };

    prefetch(0, 0);
    prefetch(1, 1);
    for (int kc = 0; kc < KC; kc++) {
        int st = kc % 3;
        if (kc + 1 < KC)
            asm volatile("cp.async.wait_group 1;" ::: "memory");
        else
            asm volatile("cp.async.wait_group 0;" ::: "memory");
        __syncthreads();
        if (kc + 2 < KC) prefetch(kc + 2, (kc + 2) % 3);
        uint32_t* As = dsm + st * 6144;
        uint32_t* Bs = dsm + st * 6144 + 4096;
#pragma unroll
        for (int kk = 0; kk < 2; kk++) {
            uint32_t aH[2][4], aL[2][4];
#pragma unroll
            for (int mi = 0; mi < 2; mi++) {
                int tt = wm * 2 + mi;
                const uint4 h = *(const uint4*)&As[((kk * 8 + tt) * 32 + lane) * 4];
                const uint4 l = *(const uint4*)&As[2048 + ((kk * 8 + tt) * 32 + lane) * 4];
                aH[mi][0] = h.x; aH[mi][1] = h.y; aH[mi][2] = h.z; aH[mi][3] = h.w;
                aL[mi][0] = l.x; aL[mi][1] = l.y; aL[mi][2] = l.z; aL[mi][3] = l.w;
            }
            uint32_t bH[4][2], bL[4][2];
#pragma unroll
            for (int nj = 0; nj < 4; nj++) {
                int nj8 = wn * 4 + nj;
                const uint2 h = *(const uint2*)&Bs[((kk * 8 + nj8) * 32 + lane) * 2];
                const uint2 l = *(const uint2*)&Bs[1024 + ((kk * 8 + nj8) * 32 + lane) * 2];
                bH[nj][0] = h.x; bH[nj][1] = h.y;
                bL[nj][0] = l.x; bL[nj][1] = l.y;
            }
#pragma unroll
            for (int mi = 0; mi < 2; mi++)
#pragma unroll
                for (int nj = 0; nj < 4; nj++)
                    MMA_F16(acc[mi][nj], aH[mi][0], aH[mi][1], aH[mi][2], aH[mi][3],
                            bH[nj][0], bH[nj][1]);
#pragma unroll
            for (int mi = 0; mi < 2; mi++)
#pragma unroll
                for (int nj = 0; nj < 4; nj++)
                    MMA_F16ACC(acx[mi][nj], aH[mi][0], aH[mi][1], aH[mi][2], aH[mi][3],
                               bL[nj][0], bL[nj][1]);
#pragma unroll
            for (int mi = 0; mi < 2; mi++)
#pragma unroll
                for (int nj = 0; nj < 4; nj++)
                    MMA_F16ACC(acx[mi][nj], aL[mi][0], aL[mi][1], aL[mi][2], aL[mi][3],
                               bH[nj][0], bH[nj][1]);
        }
    }
    __syncthreads();

    int gid = lane >> 2, tig = lane & 3;
    float sA[4][2], qA[4][2];
    if (OUT == 0) {
#pragma unroll
        for (int nj = 0; nj < 4; nj++) {
            sA[nj][0] = sA[nj][1] = 0.f;
            qA[nj][0] = qA[nj][1] = 0.f;
        }
    }
#pragma unroll
    for (int mi = 0; mi < 2; mi++) {
        int r0 = m0 + wm * 32 + mi * 16 + gid;
        bool valid = (r0 < NN);
#pragma unroll
        for (int nj = 0; nj < 4; nj++) {
            int col = n0 + wn * 32 + nj * 8 + 2 * tig;
            float bi0 = bias[col], bi1 = bias[col + 1];
            __half2 x01 = *(__half2*)&acx[mi][nj][0];
            __half2 x23 = *(__half2*)&acx[mi][nj][1];
            float v0 = acc[mi][nj][0] + __half2float(__low2half(x01))  * INV_LOSCALE + bi0;
            float v1 = acc[mi][nj][1] + __half2float(__high2half(x01)) * INV_LOSCALE + bi1;
            float v2 = acc[mi][nj][2] + __half2float(__low2half(x23))  * INV_LOSCALE + bi0;
            float v3 = acc[mi][nj][3] + __half2float(__high2half(x23)) * INV_LOSCALE + bi1;
            if (OUT == 1) {
                v0 = fmaxf(v0, 0.f); v1 = fmaxf(v1, 0.f);
                v2 = fmaxf(v2, 0.f); v3 = fmaxf(v3, 0.f);
                int r = r0 & 127;
                int t = r >> 4, gidw = r & 7, rh = (r >> 3) & 1;
                int j = col >> 1;
                int kk2 = (j >> 3) & 1, tig2 = j & 3;
                int regb = 2 * ((j >> 2) & 1);
                int base = wn * 2048 + ((kk2 * 8 + t) * 32 + gidw * 4 + tig2) * 4;
                uint32_t hi, lo;
                split_pair(v0, v1, hi, lo);
                dsm[base + rh + regb] = hi;
                dsm[4096 + base + rh + regb] = lo;
                split_pair(v2, v3, hi, lo);
                dsm[base + (rh ^ 1) + regb] = hi;
                dsm[4096 + base + (rh ^ 1) + regb] = lo;
            } else {
                if (valid) {
                    *(float2*)(C + (long)r0 * NT + col)       = make_float2(v0, v1);
                    *(float2*)(C + (long)(r0 + 8) * NT + col) = make_float2(v2, v3);
                    sA[nj][0] += v0 + v2; qA[nj][0] += v0 * v0 + v2 * v2;
                    sA[nj][1] += v1 + v3; qA[nj][1] += v1 * v1 + v3 * v3;
                }
            }
        }
    }
    if (OUT == 1) {
        __syncthreads();
        long gb = ((long)(bx * 8 + nb * 2)) * 2048;
        uint4* dh = (uint4*)(Fh + gb);
        uint4* dl = (uint4*)(Fl + gb);
        const uint4* sh_ = (const uint4*)dsm;
        const uint4* sl_ = (const uint4*)(dsm + 4096);
#pragma unroll
        for (int i = 0; i < 4; i++) {
            dh[tid + i * 256] = sh_[tid + i * 256];
            dl[tid + i * 256] = sl_[tid + i * 256];
        }
    } else {
#pragma unroll
        for (int nj = 0; nj < 4; nj++) {
#pragma unroll
            for (int m = 4; m < 32; m <<= 1) {
                sA[nj][0] += __shfl_xor_sync(0xFFFFFFFF, sA[nj][0], m);
                sA[nj][1] += __shfl_xor_sync(0xFFFFFFFF, sA[nj][1], m);
                qA[nj][0] += __shfl_xor_sync(0xFFFFFFFF, qA[nj][0], m);
                qA[nj][1] += __shfl_xor_sync(0xFFFFFFFF, qA[nj][1], m);
            }
            if (lane < 4) {
                int c = wn * 32 + nj * 8 + 2 * lane;
                atomicAdd(&bnS[c],     sA[nj][0]);
                atomicAdd(&bnS[c + 1], sA[nj][1]);
                atomicAdd(&bnQ[c],     qA[nj][0]);
                atomicAdd(&bnQ[c + 1], qA[nj][1]);
            }
        }
        __syncthreads();
        if (tid < 64) {
            atomicAdd(&sumS[n0 + tid], bnS[tid]);
            atomicAdd(&sumQ[n0 + tid], bnQ[tid]);
        }
    }
}

// ---------------- last-layer BN apply: node_rep + pool RED ----------------
__global__ void bn_apply_last_kernel(const float* __restrict__ gamma,
                                     const float* __restrict__ beta,
                                     const int* __restrict__ batch_ids,
                                     const float* __restrict__ sumS,
                                     const float* __restrict__ sumQ,
                                     float* __restrict__ out_node) {
    __shared__ __align__(16) float ssc[D], ssh[D];
    int tid = threadIdx.x;
    if (tid < D) {
        float mu = sumS[tid] * (1.0f / NN);
        float var = sumQ[tid] * (1.0f / NN) - mu * mu;
        float rs = rsqrtf(var + BN_EPS);
        float sc = gamma[tid] * rs;
        ssc[tid] = sc;
        ssh[tid] = beta[tid] - mu * sc;
    }
    __syncthreads();
    int idx = blockIdx.x * blockDim.x + tid;
    if (idx >= NN * 32) return;
    int row = idx >> 5;
    int d0  = (idx & 31) * 4;
    float4 x = *(const float4*)(g_z2 + (long)row * D + d0);
    float4 sc = *(const float4*)(ssc + d0);
    float4 sh = *(const float4*)(ssh + d0);
    float4 o;
    o.x = fmaf(sc.x, x.x, sh.x);
    o.y = fmaf(sc.y, x.y, sh.y);
    o.z = fmaf(sc.z, x.z, sh.z);
    o.w = fmaf(sc.w, x.w, sh.w);
    *(float4*)(out_node + (long)row * D + d0) = o;
    int b = batch_ids[row];
    float* gp = g_gsum + (long)b * D + d0;
    asm volatile("red.global.add.v4.f32 [%0], {%1,%2,%3,%4};"
                 :: "l"(gp), "f"(o.x), "f"(o.y), "f"(o.z), "f"(o.w) : "memory");
}
__global__ void pool_finalize_kernel(float* __restrict__ out) {
    int i = blockIdx.x * blockDim.x + threadIdx.x;
    if (i >= GG * D) return;
    int g = i >> 7;
    out[i] = g_gsum[i] / fmaxf(g_gcnt[g], 1.0f);
}

// ---------------- launch ----------------
extern "C" void kernel_launch(void* const* d_in, const int* in_sizes, int n_in,
                              void* d_out, int out_size) {
    const int* x_tokens   = (const int*)d_in[0];
    const int* ins_len    = (const int*)d_in[1];
    const int* edge_index = (const int*)d_in[2];
    const int* edge_attr  = (const int*)d_in[3];
    const int* batch_ids  = (const int*)d_in[4];
    const float* wemb  = (const float*)d_in[5];
    const float* eemb  = (const float*)d_in[6];
    const float* W1    = (const float*)d_in[7];
    const float* b1    = (const float*)d_in[8];
    const float* W2    = (const float*)d_in[9];
    const float* b2    = (const float*)d_in[10];
    const float* gamma = (const float*)d_in[11];
    const float* beta  = (const float*)d_in[12];
    float* out = (float*)d_out;
    float* out_graph = out;                 // [GG, D]
    float* out_node  = out + GG * D;        // [NN, D]

    float *ph, *pz2, *psum, *psumsq;
    uint32_t *pzah, *pzal, *pmfh, *pmfl, *pw1h, *pw1l, *pw2h, *pw2l;
    cudaGetSymbolAddress((void**)&ph,     g_h);
    cudaGetSymbolAddress((void**)&pz2,    g_z2);
    cudaGetSymbolAddress((void**)&psum,   g_sumL);
    cudaGetSymbolAddress((void**)&psumsq, g_sumsqL);
    cudaGetSymbolAddress((void**)&pzah, g_za_h);
    cudaGetSymbolAddress((void**)&pzal, g_za_l);
    cudaGetSymbolAddress((void**)&pmfh, g_mf_h);
    cudaGetSymbolAddress((void**)&pmfl, g_mf_l);
    cudaGetSymbolAddress((void**)&pw1h, g_w1h);
    cudaGetSymbolAddress((void**)&pw1l, g_w1l);
    cudaGetSymbolAddress((void**)&pw2h, g_w2h);
    cudaGetSymbolAddress((void**)&pw2l, g_w2l);

    cudaFuncSetAttribute(gemm_f16_kernel<D2, D, 1>,
                         cudaFuncAttributeMaxDynamicSharedMemorySize, GEMM_SMEM);
    cudaFuncSetAttribute(gemm_f16_kernel<D, D2, 0>,
                         cudaFuncAttributeMaxDynamicSharedMemorySize, GEMM_SMEM);

    zero_pool_kernel<<<(GG * D + 255) / 256, 256>>>();
    prolog_kernel<<<NN, 128>>>(x_tokens, ins_len, wemb, batch_ids,
                               edge_index, W1, W2);
    scan_kernel<<<1, 1024>>>();
    fill_kernel<<<(NE / 2 + 255) / 256, 256>>>(edge_index, edge_attr);

    for (int l = 0; l < NLAYERS; l++) {
        if (l == 0)
            aggregate_kernel<0><<<NN / 8, 256>>>(eemb, ph, nullptr, nullptr,
                                                 nullptr, nullptr);
        else
            aggregate_kernel<1><<<NN / 8, 256>>>(eemb, pz2,
                                                 psum + (long)(l - 1) * D,
                                                 psumsq + (long)(l - 1) * D,
                                                 gamma + (long)(l - 1) * D,
                                                 beta + (long)(l - 1) * D);
        gemm_f16_kernel<D2, D, 1><<<dim3(MBLK, 4), 256, GEMM_SMEM>>>(
            pzah, pzal, pw1h + (long)l * D * D2 / 2, pw1l + (long)l * D * D2 / 2,
            b1 + (long)l * D2, nullptr, pmfh, pmfl, nullptr, nullptr);
        gemm_f16_kernel<D, D2, 0><<<dim3(MBLK, 2), 256, GEMM_SMEM>>>(
            pmfh, pmfl, pw2h + (long)l * D2 * D / 2, pw2l + (long)l * D2 * D / 2,
            b2 + (long)l * D, pz2, nullptr, nullptr,
            psum + (long)l * D, psumsq + (long)l * D);
    }
    bn_apply_last_kernel<<<(NN * 32 + 511) / 512, 512>>>(
        gamma + (long)(NLAYERS - 1) * D, beta + (long)(NLAYERS - 1) * D,
        batch_ids, psum + (long)(NLAYERS - 1) * D, psumsq + (long)(NLAYERS - 1) * D,
        out_node);

    pool_finalize_kernel<<<(GG * D + 255) / 256, 256>>>(out_graph);
}